// round 6
// baseline (speedup 1.0000x reference)
#include <cuda_runtime.h>
#include <cstdint>

// TT layer via merged-core tf32 mma.sync GEMMs.
// Round 6: round-4 tiling (CTA 128x128, 8 warps x 32x64, 2 CTA/SM) +
// round-5 K-permuted operands for LDS.128 fragment loads.
// out[n,ab,cd] = relu( sum H12[ab,(s,ij)] x[n,ij,kl] H34[(cd,s),kl] + bias )
// GEMM1 per n: M1[cds, ij] = H34 . Xr[n]^T   M=1024 N=256 K=256
// GEMM2 per n: out[ab, cd] = H12 . M1[n]^T   M=256  N=256 K=1024 (+bias,relu)
// K dims permuted within 32-blocks: p = (k%4)*8 + k/4, so per-lane fragment
// elements are contiguous float4s.

__device__ float g_H34[262144];
__device__ float g_H12[262144];
__device__ float g_Xr[67108864];   // RNA-rounded, K-permuted x (256 MB)
__device__ float g_M1[268435456];  // K-permuted M1 (1 GiB)

__device__ __forceinline__ float rna_tf32(float f) {
  uint32_t r; asm("cvt.rna.tf32.f32 %0, %1;" : "=r"(r) : "f"(f));
  return __uint_as_float(r);
}
__device__ __forceinline__ int perm32(int v) { return ((v & 3) << 3) | (v >> 2); }
__device__ __forceinline__ uint32_t smem_u32(const void* p) {
  uint32_t a;
  asm("{ .reg .u64 t; cvta.to.shared.u64 t, %1; cvt.u32.u64 %0, t; }" : "=r"(a) : "l"(p));
  return a;
}
__device__ __forceinline__ void cp16(uint32_t s, const float* g) {
  asm volatile("cp.async.cg.shared.global [%0], [%1], 16;" :: "r"(s), "l"(g));
}
__device__ __forceinline__ void mma_tf32(float* c, const uint32_t* a, const uint32_t* b) {
  asm volatile(
      "mma.sync.aligned.m16n8k8.row.col.f32.tf32.tf32.f32 "
      "{%0,%1,%2,%3}, {%4,%5,%6,%7}, {%8,%9}, {%0,%1,%2,%3};"
      : "+f"(c[0]), "+f"(c[1]), "+f"(c[2]), "+f"(c[3])
      : "r"(a[0]), "r"(a[1]), "r"(a[2]), "r"(a[3]), "r"(b[0]), "r"(b[1]));
}

// ---------------- precompute (RNA-round + K-permute) ----------------
__global__ void prep_h34(const float* __restrict__ G3, const float* __restrict__ G4) {
  int e = blockIdx.x * 256 + threadIdx.x;
  int col = e & 255, row = e >> 8;
  int s = row & 3, cd = row >> 2;
  int c = cd >> 4, d = cd & 15, k = col >> 4, l = col & 15;
  float acc = 0.f;
#pragma unroll
  for (int tt = 0; tt < 4; ++tt)
    acc += G3[((c * 16 + k) * 4 + s) * 4 + tt] * G4[(d * 16 + l) * 4 + tt];
  g_H34[(row << 8) | (col & ~31) | perm32(col & 31)] = rna_tf32(acc);
}
__global__ void prep_h12(const float* __restrict__ G1, const float* __restrict__ G2) {
  int e = blockIdx.x * 256 + threadIdx.x;
  int ab = e >> 10, k = e & 1023;
  int s = k >> 8, ij = k & 255;
  int a = ab >> 4, b = ab & 15, i = ij >> 4, j = ij & 15;
  float acc = 0.f;
#pragma unroll
  for (int r = 0; r < 4; ++r)
    acc += G1[(a * 16 + i) * 4 + r] * G2[((b * 16 + j) * 4 + r) * 4 + s];
  g_H12[(ab << 10) | (k & ~31) | perm32(k & 31)] = rna_tf32(acc);
}
__global__ __launch_bounds__(256) void round_x(const float* __restrict__ x) {
  size_t idx = (size_t)blockIdx.x * 256 + threadIdx.x;
  float4 v = *(const float4*)(x + idx * 4);
  size_t e = idx * 4;
  float* o = g_Xr + (e & ~(size_t)31) + (int)((e & 31) >> 2);
  o[0]  = rna_tf32(v.x);
  o[8]  = rna_tf32(v.y);
  o[16] = rna_tf32(v.z);
  o[24] = rna_tf32(v.w);
}

// ---------------- batched GEMM: C[n] = A . B[n]^T ----------------
// A [Mtotal x K]; B[n] [256 x K]; both K-major, K-permuted per 32-block.
// C[n] [Mtotal x 256] row-major. CTA 128x128, 8 warps of 32(m) x 64(n).
#define PAD 36
#define HALF_F 4608   // 128 * 36 floats
#define STG_F 9216

__global__ __launch_bounds__(256, 2) void tt_gemm(
    const float* __restrict__ A, const float* __restrict__ Bbase, long long bStride,
    float* __restrict__ Cbase, long long cStride, int K,
    const float* __restrict__ bias, int permOut) {
  extern __shared__ __align__(16) float sm[];
  const int t = threadIdx.x;
  const int lane = t & 31, wid = t >> 5;
  const int grp = lane >> 2, tg = lane & 3;
  const int nt = blockIdx.x & 1, mt = blockIdx.x >> 1;
  const int n = blockIdx.y;
  const int wm = (wid & 3) * 32, wn = (wid >> 2) * 64;

  const float* Am = A + (long long)mt * 128 * K;
  const float* Bn = Bbase + (long long)n * bStride + (long long)nt * 128 * K;

  const int srow = t >> 3, sq = t & 7;
  const uint32_t base = smem_u32(sm);
  const uint32_t stA = base + (uint32_t)(srow * PAD + sq * 4) * 4u;
  const uint32_t stB = stA + HALF_F * 4u;

  float acc[2][8][4];
#pragma unroll
  for (int mi = 0; mi < 2; ++mi)
#pragma unroll
    for (int ni = 0; ni < 8; ++ni)
#pragma unroll
      for (int q = 0; q < 4; ++q) acc[mi][ni][q] = 0.f;

  const int nch = K >> 5;

#pragma unroll
  for (int pch = 0; pch < 2; ++pch) {
    const float* ga = Am + pch * 32;
    const float* gb = Bn + pch * 32;
    const uint32_t so = (uint32_t)pch * STG_F * 4u;
#pragma unroll
    for (int rep = 0; rep < 4; ++rep) {
      cp16(stA + so + rep * 32u * PAD * 4u, ga + (long long)(srow + rep * 32) * K + sq * 4);
      cp16(stB + so + rep * 32u * PAD * 4u, gb + (long long)(srow + rep * 32) * K + sq * 4);
    }
    asm volatile("cp.async.commit_group;" ::: "memory");
  }

  for (int ch = 0; ch < nch; ++ch) {
    const int st = ch & 1;
    asm volatile("cp.async.wait_group 1;" ::: "memory");
    __syncthreads();

    const float* sA = sm + st * STG_F;
    const float* sB = sA + HALF_F;
#pragma unroll
    for (int sel = 0; sel < 2; ++sel) {
      // A fragments for 2 k-steps (kk = 2*sel, 2*sel+1): 4x LDS.128
      float4 alo[2], ahi[2];
#pragma unroll
      for (int mi = 0; mi < 2; ++mi) {
        const float* pa = sA + (wm + mi * 16 + grp) * PAD + tg * 8 + sel * 4;
        alo[mi] = *(const float4*)pa;
        ahi[mi] = *(const float4*)(pa + 8 * PAD);
      }
      uint32_t aA[2][4], aB[2][4];
#pragma unroll
      for (int mi = 0; mi < 2; ++mi) {
        aA[mi][0] = __float_as_uint(alo[mi].x); aA[mi][1] = __float_as_uint(ahi[mi].x);
        aA[mi][2] = __float_as_uint(alo[mi].y); aA[mi][3] = __float_as_uint(ahi[mi].y);
        aB[mi][0] = __float_as_uint(alo[mi].z); aB[mi][1] = __float_as_uint(ahi[mi].z);
        aB[mi][2] = __float_as_uint(alo[mi].w); aB[mi][3] = __float_as_uint(ahi[mi].w);
      }
      // B fragments in two halves of 4 columns (reg pressure)
#pragma unroll
      for (int nh = 0; nh < 2; ++nh) {
        float4 bb[4];
#pragma unroll
        for (int nq = 0; nq < 4; ++nq)
          bb[nq] = *(const float4*)(sB + (wn + (nh * 4 + nq) * 8 + grp) * PAD + tg * 8 + sel * 4);
#pragma unroll
        for (int nq = 0; nq < 4; ++nq) {
          uint32_t b0[2] = { __float_as_uint(bb[nq].x), __float_as_uint(bb[nq].y) };
          uint32_t b1[2] = { __float_as_uint(bb[nq].z), __float_as_uint(bb[nq].w) };
#pragma unroll
          for (int mi = 0; mi < 2; ++mi) {
            mma_tf32(acc[mi][nh * 4 + nq], aA[mi], b0);
            mma_tf32(acc[mi][nh * 4 + nq], aB[mi], b1);
          }
        }
      }
    }
    __syncthreads();
    if (ch + 2 < nch) {
      const float* ga = Am + (ch + 2) * 32;
      const float* gb = Bn + (ch + 2) * 32;
      const uint32_t so = (uint32_t)st * STG_F * 4u;
#pragma unroll
      for (int rep = 0; rep < 4; ++rep) {
        cp16(stA + so + rep * 32u * PAD * 4u, ga + (long long)(srow + rep * 32) * K + sq * 4);
        cp16(stB + so + rep * 32u * PAD * 4u, gb + (long long)(srow + rep * 32) * K + sq * 4);
      }
    }
    asm volatile("cp.async.commit_group;" ::: "memory");
  }

  float* Cn = Cbase + (long long)n * cStride;
#pragma unroll
  for (int mi = 0; mi < 2; ++mi) {
    int r0 = mt * 128 + wm + mi * 16 + grp;
#pragma unroll
    for (int ni = 0; ni < 8; ++ni) {
      int col = nt * 128 + wn + ni * 8 + 2 * tg;
      float v0 = acc[mi][ni][0], v1 = acc[mi][ni][1];
      float v2 = acc[mi][ni][2], v3 = acc[mi][ni][3];
      if (bias) {
        v0 = fmaxf(v0 + bias[r0 * 256 + col], 0.f);
        v1 = fmaxf(v1 + bias[r0 * 256 + col + 1], 0.f);
        v2 = fmaxf(v2 + bias[(r0 + 8) * 256 + col], 0.f);
        v3 = fmaxf(v3 + bias[(r0 + 8) * 256 + col + 1], 0.f);
        *(float2*)(Cn + (long long)r0 * 256 + col) = make_float2(v0, v1);
        *(float2*)(Cn + (long long)(r0 + 8) * 256 + col) = make_float2(v2, v3);
      } else if (permOut) {
        int p0 = (col & ~31) | perm32(col & 31);
        float* c0 = Cn + (long long)r0 * 256;
        float* c1 = Cn + (long long)(r0 + 8) * 256;
        c0[p0]     = rna_tf32(v0);
        c0[p0 + 8] = rna_tf32(v1);
        c1[p0]     = rna_tf32(v2);
        c1[p0 + 8] = rna_tf32(v3);
      }
    }
  }
}

// ---------------- launch ----------------
extern "C" void kernel_launch(void* const* d_in, const int* in_sizes, int n_in,
                              void* d_out, int out_size) {
  const float* x    = (const float*)d_in[0];
  const float* G1   = (const float*)d_in[1];
  const float* G2   = (const float*)d_in[2];
  const float* G3   = (const float*)d_in[3];
  const float* G4   = (const float*)d_in[4];
  const float* bias = (const float*)d_in[5];
  float* out = (float*)d_out;
  const int nb = in_sizes[0] / 65536;

  float *pH34, *pH12, *pM1, *pXr;
  cudaGetSymbolAddress((void**)&pH34, g_H34);
  cudaGetSymbolAddress((void**)&pH12, g_H12);
  cudaGetSymbolAddress((void**)&pM1, g_M1);
  cudaGetSymbolAddress((void**)&pXr, g_Xr);

  const int smem = 2 * STG_F * 4;  // 73728 B
  cudaFuncSetAttribute(tt_gemm, cudaFuncAttributeMaxDynamicSharedMemorySize, smem);

  prep_h34<<<1024, 256>>>(G3, G4);
  prep_h12<<<1024, 256>>>(G1, G2);
  round_x<<<in_sizes[0] / 1024, 256>>>(x);

  // GEMM1: M1[n] = H34 (1024xK256) . Xr[n]^T : 8 mtiles x 2 ntiles
  tt_gemm<<<dim3(16, nb), 256, smem>>>(pH34, pXr, 65536LL, pM1, 262144LL, 256,
                                       nullptr, 1);
  // GEMM2: out[n] = H12 (256xK1024) . M1[n]^T : 2 mtiles x 2 ntiles
  tt_gemm<<<dim3(4, nb), 256, smem>>>(pH12, pM1, 262144LL, out, 65536LL, 1024,
                                      bias, 0);
}

// round 7
// speedup vs baseline: 2.2401x; 2.2401x over previous
#include <cuda_runtime.h>
#include <cuda_fp16.h>
#include <cstdint>

// TT layer via merged-core fp16 mma.sync GEMMs (m16n8k16, fp32 accumulate).
// fp16 mantissa == tf32 mantissa (10 bits), values are O(1) -> same accuracy
// as the tf32 path, 2x MAC/instr and half the operand bytes.
// out[n,ab,cd] = relu( sum H12[ab,(s,ij)] x[n,ij,kl] H34[(cd,s),kl] + bias )
// GEMM1 per n: M1[cds, ij] = H34 . Xr[n]^T   M=1024 N=256 K=256
// GEMM2 per n: out[ab, cd] = H12 . M1[n]^T   M=256  N=256 K=1024 (+bias,relu)

__device__ __half g_H34[262144];
__device__ __half g_H12[262144];
__device__ __half g_Xr[67108864];   // RNE-rounded x (128 MB)
__device__ __half g_M1[268435456];  // M1 fp16 (512 MB)

__device__ __forceinline__ uint32_t smem_u32(const void* p) {
  uint32_t a;
  asm("{ .reg .u64 t; cvta.to.shared.u64 t, %1; cvt.u32.u64 %0, t; }" : "=r"(a) : "l"(p));
  return a;
}
__device__ __forceinline__ void cp16(uint32_t s, const __half* g) {
  asm volatile("cp.async.cg.shared.global [%0], [%1], 16;" :: "r"(s), "l"(g));
}
__device__ __forceinline__ void mma_f16(float* c, const uint32_t* a, const uint32_t* b) {
  asm volatile(
      "mma.sync.aligned.m16n8k16.row.col.f32.f16.f16.f32 "
      "{%0,%1,%2,%3}, {%4,%5,%6,%7}, {%8,%9}, {%0,%1,%2,%3};"
      : "+f"(c[0]), "+f"(c[1]), "+f"(c[2]), "+f"(c[3])
      : "r"(a[0]), "r"(a[1]), "r"(a[2]), "r"(a[3]), "r"(b[0]), "r"(b[1]));
}
__device__ __forceinline__ uint32_t lds32(const __half* p) {
  return *(const uint32_t*)p;
}

// ---------------- precompute (fp32 math, RNE fp16 store) ----------------
__global__ void prep_h34(const float* __restrict__ G3, const float* __restrict__ G4) {
  int e = blockIdx.x * 256 + threadIdx.x;
  int col = e & 255, row = e >> 8;
  int s = row & 3, cd = row >> 2;
  int c = cd >> 4, d = cd & 15, k = col >> 4, l = col & 15;
  float acc = 0.f;
#pragma unroll
  for (int tt = 0; tt < 4; ++tt)
    acc += G3[((c * 16 + k) * 4 + s) * 4 + tt] * G4[(d * 16 + l) * 4 + tt];
  g_H34[e] = __float2half_rn(acc);
}
__global__ void prep_h12(const float* __restrict__ G1, const float* __restrict__ G2) {
  int e = blockIdx.x * 256 + threadIdx.x;
  int ab = e >> 10, k = e & 1023;
  int s = k >> 8, ij = k & 255;
  int a = ab >> 4, b = ab & 15, i = ij >> 4, j = ij & 15;
  float acc = 0.f;
#pragma unroll
  for (int r = 0; r < 4; ++r)
    acc += G1[(a * 16 + i) * 4 + r] * G2[((b * 16 + j) * 4 + r) * 4 + s];
  g_H12[e] = __float2half_rn(acc);
}
__global__ __launch_bounds__(256) void round_x(const float* __restrict__ x) {
  size_t idx = (size_t)blockIdx.x * 256 + threadIdx.x;
  float4 v = *(const float4*)(x + idx * 4);
  __half2 h0 = __floats2half2_rn(v.x, v.y);
  __half2 h1 = __floats2half2_rn(v.z, v.w);
  uint2 o = { *(uint32_t*)&h0, *(uint32_t*)&h1 };
  *(uint2*)(g_Xr + idx * 4) = o;
}

// ---------------- batched fp16 GEMM: C[n] = A . B[n]^T ----------------
// A [Mtotal x K] K-major half; B[n] [256 x K] K-major half.
// C[n]: fp32 (bias+relu) if bias != null, else fp16.
// CTA tile 128x128, 8 warps of 32(m) x 64(n). K-chunk 32, 2-stage cp.async.
#define PADH 40
#define TILE_H 5120   // 128 * PADH halves per operand tile
#define STG_H 10240   // halves per stage (A + B)

__global__ __launch_bounds__(256, 2) void tt_gemm(
    const __half* __restrict__ A, const __half* __restrict__ Bbase, long long bStride,
    void* __restrict__ Cbase, long long cStride, int K,
    const float* __restrict__ bias) {
  extern __shared__ __align__(16) __half smh[];
  const int t = threadIdx.x;
  const int lane = t & 31, wid = t >> 5;
  const int grp = lane >> 2, tg = lane & 3;
  const int nt = blockIdx.x & 1, mt = blockIdx.x >> 1;
  const int n = blockIdx.y;
  const int wm = (wid & 3) * 32, wn = (wid >> 2) * 64;

  const __half* Am = A + (long long)mt * 128 * K;
  const __half* Bn = Bbase + (long long)n * bStride + (long long)nt * 128 * K;

  // cp.async mapping: row = t>>2 (+64 per rep), q = t&3 (16B = 8 halves each)
  const int srow = t >> 2, sq = t & 3;
  const uint32_t base = smem_u32(smh);
  const uint32_t stA = base + (uint32_t)(srow * PADH + sq * 8) * 2u;
  const uint32_t stB = stA + TILE_H * 2u;

  float acc[2][8][4];
#pragma unroll
  for (int mi = 0; mi < 2; ++mi)
#pragma unroll
    for (int ni = 0; ni < 8; ++ni)
#pragma unroll
      for (int q = 0; q < 4; ++q) acc[mi][ni][q] = 0.f;

  const int nch = K >> 5;

#pragma unroll
  for (int pch = 0; pch < 2; ++pch) {
    const __half* ga = Am + pch * 32;
    const __half* gb = Bn + pch * 32;
    const uint32_t so = (uint32_t)pch * STG_H * 2u;
#pragma unroll
    for (int rep = 0; rep < 2; ++rep) {
      cp16(stA + so + rep * 64u * PADH * 2u, ga + (long long)(srow + rep * 64) * K + sq * 8);
      cp16(stB + so + rep * 64u * PADH * 2u, gb + (long long)(srow + rep * 64) * K + sq * 8);
    }
    asm volatile("cp.async.commit_group;" ::: "memory");
  }

  for (int ch = 0; ch < nch; ++ch) {
    const int st = ch & 1;
    asm volatile("cp.async.wait_group 1;" ::: "memory");
    __syncthreads();

    const __half* sA = smh + st * STG_H;
    const __half* sB = sA + TILE_H;
#pragma unroll
    for (int sel = 0; sel < 2; ++sel) {  // two k16 steps per 32-chunk
      const int k0 = sel * 16 + 2 * tg;
      uint32_t a[2][4];
#pragma unroll
      for (int mi = 0; mi < 2; ++mi) {
        const __half* pa = sA + (wm + mi * 16 + grp) * PADH + k0;
        a[mi][0] = lds32(pa);
        a[mi][1] = lds32(pa + 8 * PADH);
        a[mi][2] = lds32(pa + 8);
        a[mi][3] = lds32(pa + 8 * PADH + 8);
      }
#pragma unroll
      for (int ni = 0; ni < 8; ++ni) {
        const __half* pb = sB + (wn + ni * 8 + grp) * PADH + k0;
        uint32_t b[2] = { lds32(pb), lds32(pb + 8) };
        mma_f16(acc[0][ni], a[0], b);
        mma_f16(acc[1][ni], a[1], b);
      }
    }
    __syncthreads();
    if (ch + 2 < nch) {
      const __half* ga = Am + (ch + 2) * 32;
      const __half* gb = Bn + (ch + 2) * 32;
      const uint32_t so = (uint32_t)st * STG_H * 2u;
#pragma unroll
      for (int rep = 0; rep < 2; ++rep) {
        cp16(stA + so + rep * 64u * PADH * 2u, ga + (long long)(srow + rep * 64) * K + sq * 8);
        cp16(stB + so + rep * 64u * PADH * 2u, gb + (long long)(srow + rep * 64) * K + sq * 8);
      }
    }
    asm volatile("cp.async.commit_group;" ::: "memory");
  }

  if (bias) {
    float* Cn = (float*)Cbase + (long long)n * cStride;
#pragma unroll
    for (int mi = 0; mi < 2; ++mi) {
      int r0 = mt * 128 + wm + mi * 16 + grp;
#pragma unroll
      for (int ni = 0; ni < 8; ++ni) {
        int col = nt * 128 + wn + ni * 8 + 2 * tg;
        float v0 = fmaxf(acc[mi][ni][0] + bias[r0 * 256 + col], 0.f);
        float v1 = fmaxf(acc[mi][ni][1] + bias[r0 * 256 + col + 1], 0.f);
        float v2 = fmaxf(acc[mi][ni][2] + bias[(r0 + 8) * 256 + col], 0.f);
        float v3 = fmaxf(acc[mi][ni][3] + bias[(r0 + 8) * 256 + col + 1], 0.f);
        *(float2*)(Cn + (long long)r0 * 256 + col) = make_float2(v0, v1);
        *(float2*)(Cn + (long long)(r0 + 8) * 256 + col) = make_float2(v2, v3);
      }
    }
  } else {
    __half* Cn = (__half*)Cbase + (long long)n * cStride;
#pragma unroll
    for (int mi = 0; mi < 2; ++mi) {
      int r0 = mt * 128 + wm + mi * 16 + grp;
#pragma unroll
      for (int ni = 0; ni < 8; ++ni) {
        int col = nt * 128 + wn + ni * 8 + 2 * tg;
        __half2 h01 = __floats2half2_rn(acc[mi][ni][0], acc[mi][ni][1]);
        __half2 h23 = __floats2half2_rn(acc[mi][ni][2], acc[mi][ni][3]);
        *(uint32_t*)(Cn + (long long)r0 * 256 + col) = *(uint32_t*)&h01;
        *(uint32_t*)(Cn + (long long)(r0 + 8) * 256 + col) = *(uint32_t*)&h23;
      }
    }
  }
}

// ---------------- launch ----------------
extern "C" void kernel_launch(void* const* d_in, const int* in_sizes, int n_in,
                              void* d_out, int out_size) {
  const float* x    = (const float*)d_in[0];
  const float* G1   = (const float*)d_in[1];
  const float* G2   = (const float*)d_in[2];
  const float* G3   = (const float*)d_in[3];
  const float* G4   = (const float*)d_in[4];
  const float* bias = (const float*)d_in[5];
  float* out = (float*)d_out;
  const int nb = in_sizes[0] / 65536;

  __half *pH34, *pH12, *pM1, *pXr;
  cudaGetSymbolAddress((void**)&pH34, g_H34);
  cudaGetSymbolAddress((void**)&pH12, g_H12);
  cudaGetSymbolAddress((void**)&pM1, g_M1);
  cudaGetSymbolAddress((void**)&pXr, g_Xr);

  const int smem = 2 * STG_H * 2;  // 40960 B
  cudaFuncSetAttribute(tt_gemm, cudaFuncAttributeMaxDynamicSharedMemorySize, smem);

  prep_h34<<<1024, 256>>>(G3, G4);
  prep_h12<<<1024, 256>>>(G1, G2);
  round_x<<<in_sizes[0] / 1024, 256>>>(x);

  // GEMM1: M1[n] = H34 (1024xK256) . Xr[n]^T : 8 mtiles x 2 ntiles
  tt_gemm<<<dim3(16, nb), 256, smem>>>(pH34, pXr, 65536LL, pM1, 262144LL, 256,
                                       nullptr);
  // GEMM2: out[n] = H12 (256xK1024) . M1[n]^T : 2 mtiles x 2 ntiles (+bias,relu)
  tt_gemm<<<dim3(4, nb), 256, smem>>>(pH12, pM1, 262144LL, out, 65536LL, 1024,
                                      bias);
}

// round 8
// speedup vs baseline: 2.4340x; 1.0866x over previous
#include <cuda_runtime.h>
#include <cuda_fp16.h>
#include <cstdint>

// TT layer via merged-core fp16 mma.sync GEMMs (m16n8k16, fp32 accumulate).
// Round 8: ldmatrix.x4 fragment loads + 3-stage cp.async pipeline with a
// single __syncthreads per K-chunk.
// out[n,ab,cd] = relu( sum H12[ab,(s,ij)] x[n,ij,kl] H34[(cd,s),kl] + bias )
// GEMM1 per n: M1[cds, ij] = H34 . Xr[n]^T   M=1024 N=256 K=256
// GEMM2 per n: out[ab, cd] = H12 . M1[n]^T   M=256  N=256 K=1024 (+bias,relu)

__device__ __half g_H34[262144];
__device__ __half g_H12[262144];
__device__ __half g_Xr[67108864];   // RNE-rounded x (128 MB)
__device__ __half g_M1[268435456];  // M1 fp16 (512 MB)

__device__ __forceinline__ uint32_t smem_u32(const void* p) {
  uint32_t a;
  asm("{ .reg .u64 t; cvta.to.shared.u64 t, %1; cvt.u32.u64 %0, t; }" : "=r"(a) : "l"(p));
  return a;
}
__device__ __forceinline__ void cp16(uint32_t s, const __half* g) {
  asm volatile("cp.async.cg.shared.global [%0], [%1], 16;" :: "r"(s), "l"(g));
}
__device__ __forceinline__ void mma_f16(float* c, const uint32_t* a, uint32_t b0, uint32_t b1) {
  asm volatile(
      "mma.sync.aligned.m16n8k16.row.col.f32.f16.f16.f32 "
      "{%0,%1,%2,%3}, {%4,%5,%6,%7}, {%8,%9}, {%0,%1,%2,%3};"
      : "+f"(c[0]), "+f"(c[1]), "+f"(c[2]), "+f"(c[3])
      : "r"(a[0]), "r"(a[1]), "r"(a[2]), "r"(a[3]), "r"(b0), "r"(b1));
}
__device__ __forceinline__ void ldsm_x4(uint32_t* r, uint32_t addr) {
  asm volatile("ldmatrix.sync.aligned.m8n8.x4.shared.b16 {%0,%1,%2,%3}, [%4];"
               : "=r"(r[0]), "=r"(r[1]), "=r"(r[2]), "=r"(r[3]) : "r"(addr));
}

// ---------------- precompute (fp32 math, RNE fp16 store) ----------------
__global__ void prep_h34(const float* __restrict__ G3, const float* __restrict__ G4) {
  int e = blockIdx.x * 256 + threadIdx.x;
  int col = e & 255, row = e >> 8;
  int s = row & 3, cd = row >> 2;
  int c = cd >> 4, d = cd & 15, k = col >> 4, l = col & 15;
  float acc = 0.f;
#pragma unroll
  for (int tt = 0; tt < 4; ++tt)
    acc += G3[((c * 16 + k) * 4 + s) * 4 + tt] * G4[(d * 16 + l) * 4 + tt];
  g_H34[e] = __float2half_rn(acc);
}
__global__ void prep_h12(const float* __restrict__ G1, const float* __restrict__ G2) {
  int e = blockIdx.x * 256 + threadIdx.x;
  int ab = e >> 10, k = e & 1023;
  int s = k >> 8, ij = k & 255;
  int a = ab >> 4, b = ab & 15, i = ij >> 4, j = ij & 15;
  float acc = 0.f;
#pragma unroll
  for (int r = 0; r < 4; ++r)
    acc += G1[(a * 16 + i) * 4 + r] * G2[((b * 16 + j) * 4 + r) * 4 + s];
  g_H12[e] = __float2half_rn(acc);
}
__global__ __launch_bounds__(256) void round_x(const float* __restrict__ x) {
  size_t idx = (size_t)blockIdx.x * 256 + threadIdx.x;
  float4 v = *(const float4*)(x + idx * 4);
  __half2 h0 = __floats2half2_rn(v.x, v.y);
  __half2 h1 = __floats2half2_rn(v.z, v.w);
  uint2 o = { *(uint32_t*)&h0, *(uint32_t*)&h1 };
  *(uint2*)(g_Xr + idx * 4) = o;
}

// ---------------- batched fp16 GEMM: C[n] = A . B[n]^T ----------------
// A [Mtotal x K] K-major half; B[n] [256 x K] K-major half.
// C[n]: fp32 (bias+relu) if bias != null, else fp16.
// CTA 128x128, 8 warps of 32(m) x 64(n). K-chunk 32, 3-stage cp.async.
#define PADH 40
#define TILE_H 5120   // 128 * PADH halves per operand tile
#define STG_H 10240   // halves per stage (A + B)

__global__ __launch_bounds__(256, 2) void tt_gemm(
    const __half* __restrict__ A, const __half* __restrict__ Bbase, long long bStride,
    void* __restrict__ Cbase, long long cStride, int K,
    const float* __restrict__ bias) {
  extern __shared__ __align__(16) __half smh[];
  const int t = threadIdx.x;
  const int lane = t & 31, wid = t >> 5;
  const int grp = lane >> 2, tg = lane & 3;
  const int nt = blockIdx.x & 1, mt = blockIdx.x >> 1;
  const int n = blockIdx.y;
  const int wm = (wid & 3) * 32, wn = (wid >> 2) * 64;

  const __half* Am = A + (long long)mt * 128 * K;
  const __half* Bn = Bbase + (long long)n * bStride + (long long)nt * 128 * K;

  // cp.async mapping: row = t>>2 (+64 per rep), q = t&3 (16B each)
  const int srow = t >> 2, sq = t & 3;
  const uint32_t base = smem_u32(smh);
  const uint32_t stA = base + (uint32_t)(srow * PADH + sq * 8) * 2u;
  const uint32_t stB = stA + TILE_H * 2u;

  // ldmatrix per-lane base offsets (bytes from stage base)
  // A (mi): rows wm + mi*16 + (lane&15), col half-offset (lane>>4)*8
  uint32_t aOff[2];
#pragma unroll
  for (int mi = 0; mi < 2; ++mi)
    aOff[mi] = (uint32_t)((wm + mi * 16 + (lane & 15)) * PADH + (lane >> 4) * 8) * 2u;
  // B (q): rows wn + q*16 + (lane&7) + ((lane>>4)<<3), col ((lane>>3)&1)*8
  uint32_t bOff[4];
#pragma unroll
  for (int q = 0; q < 4; ++q)
    bOff[q] = (uint32_t)((wn + q * 16 + (lane & 7) + ((lane >> 4) << 3)) * PADH +
                         (((lane >> 3) & 1) << 3)) * 2u + TILE_H * 2u;

  float acc[2][8][4];
#pragma unroll
  for (int mi = 0; mi < 2; ++mi)
#pragma unroll
    for (int ni = 0; ni < 8; ++ni)
#pragma unroll
      for (int q = 0; q < 4; ++q) acc[mi][ni][q] = 0.f;

  const int nch = K >> 5;

  // prologue: chunks 0,1 -> stages 0,1
#pragma unroll
  for (int pch = 0; pch < 2; ++pch) {
    const __half* ga = Am + pch * 32;
    const __half* gb = Bn + pch * 32;
    const uint32_t so = (uint32_t)pch * STG_H * 2u;
#pragma unroll
    for (int rep = 0; rep < 2; ++rep) {
      cp16(stA + so + rep * 64u * PADH * 2u, ga + (long long)(srow + rep * 64) * K + sq * 8);
      cp16(stB + so + rep * 64u * PADH * 2u, gb + (long long)(srow + rep * 64) * K + sq * 8);
    }
    asm volatile("cp.async.commit_group;" ::: "memory");
  }

  int st = 0, pst = 2;  // current read stage, prefetch-write stage
  for (int ch = 0; ch < nch; ++ch) {
    asm volatile("cp.async.wait_group 1;" ::: "memory");
    __syncthreads();

    // prefetch chunk ch+2 into stage pst (safe: sync above proves all warps
    // finished reading that stage at chunk ch-1)
    if (ch + 2 < nch) {
      const __half* ga = Am + (ch + 2) * 32;
      const __half* gb = Bn + (ch + 2) * 32;
      const uint32_t so = (uint32_t)pst * STG_H * 2u;
#pragma unroll
      for (int rep = 0; rep < 2; ++rep) {
        cp16(stA + so + rep * 64u * PADH * 2u, ga + (long long)(srow + rep * 64) * K + sq * 8);
        cp16(stB + so + rep * 64u * PADH * 2u, gb + (long long)(srow + rep * 64) * K + sq * 8);
      }
    }
    asm volatile("cp.async.commit_group;" ::: "memory");

    const uint32_t sbase = base + (uint32_t)st * STG_H * 2u;
#pragma unroll
    for (int sel = 0; sel < 2; ++sel) {  // two k16 steps
      const uint32_t ko = (uint32_t)sel * 32u;  // 16 halves
      uint32_t a[2][4], b[4][4];
      ldsm_x4(a[0], sbase + aOff[0] + ko);
      ldsm_x4(a[1], sbase + aOff[1] + ko);
#pragma unroll
      for (int q = 0; q < 4; ++q) ldsm_x4(b[q], sbase + bOff[q] + ko);
#pragma unroll
      for (int q = 0; q < 4; ++q) {
#pragma unroll
        for (int mi = 0; mi < 2; ++mi) {
          mma_f16(acc[mi][2 * q],     a[mi], b[q][0], b[q][1]);
          mma_f16(acc[mi][2 * q + 1], a[mi], b[q][2], b[q][3]);
        }
      }
    }
    st = (st + 1) % 3;
    pst = (pst + 1) % 3;
  }

  if (bias) {
    float* Cn = (float*)Cbase + (long long)n * cStride;
#pragma unroll
    for (int mi = 0; mi < 2; ++mi) {
      int r0 = mt * 128 + wm + mi * 16 + grp;
#pragma unroll
      for (int ni = 0; ni < 8; ++ni) {
        int col = nt * 128 + wn + ni * 8 + 2 * tg;
        float v0 = fmaxf(acc[mi][ni][0] + bias[r0 * 256 + col], 0.f);
        float v1 = fmaxf(acc[mi][ni][1] + bias[r0 * 256 + col + 1], 0.f);
        float v2 = fmaxf(acc[mi][ni][2] + bias[(r0 + 8) * 256 + col], 0.f);
        float v3 = fmaxf(acc[mi][ni][3] + bias[(r0 + 8) * 256 + col + 1], 0.f);
        *(float2*)(Cn + (long long)r0 * 256 + col) = make_float2(v0, v1);
        *(float2*)(Cn + (long long)(r0 + 8) * 256 + col) = make_float2(v2, v3);
      }
    }
  } else {
    __half* Cn = (__half*)Cbase + (long long)n * cStride;
#pragma unroll
    for (int mi = 0; mi < 2; ++mi) {
      int r0 = mt * 128 + wm + mi * 16 + grp;
#pragma unroll
      for (int ni = 0; ni < 8; ++ni) {
        int col = nt * 128 + wn + ni * 8 + 2 * tg;
        __half2 h01 = __floats2half2_rn(acc[mi][ni][0], acc[mi][ni][1]);
        __half2 h23 = __floats2half2_rn(acc[mi][ni][2], acc[mi][ni][3]);
        *(uint32_t*)(Cn + (long long)r0 * 256 + col) = *(uint32_t*)&h01;
        *(uint32_t*)(Cn + (long long)(r0 + 8) * 256 + col) = *(uint32_t*)&h23;
      }
    }
  }
}

// ---------------- launch ----------------
extern "C" void kernel_launch(void* const* d_in, const int* in_sizes, int n_in,
                              void* d_out, int out_size) {
  const float* x    = (const float*)d_in[0];
  const float* G1   = (const float*)d_in[1];
  const float* G2   = (const float*)d_in[2];
  const float* G3   = (const float*)d_in[3];
  const float* G4   = (const float*)d_in[4];
  const float* bias = (const float*)d_in[5];
  float* out = (float*)d_out;
  const int nb = in_sizes[0] / 65536;

  __half *pH34, *pH12, *pM1, *pXr;
  cudaGetSymbolAddress((void**)&pH34, g_H34);
  cudaGetSymbolAddress((void**)&pH12, g_H12);
  cudaGetSymbolAddress((void**)&pM1, g_M1);
  cudaGetSymbolAddress((void**)&pXr, g_Xr);

  const int smem = 3 * STG_H * 2;  // 61440 B
  cudaFuncSetAttribute(tt_gemm, cudaFuncAttributeMaxDynamicSharedMemorySize, smem);

  prep_h34<<<1024, 256>>>(G3, G4);
  prep_h12<<<1024, 256>>>(G1, G2);
  round_x<<<in_sizes[0] / 1024, 256>>>(x);

  // GEMM1: M1[n] = H34 (1024xK256) . Xr[n]^T : 8 mtiles x 2 ntiles
  tt_gemm<<<dim3(16, nb), 256, smem>>>(pH34, pXr, 65536LL, pM1, 262144LL, 256,
                                       nullptr);
  // GEMM2: out[n] = H12 (256xK1024) . M1[n]^T : 2 mtiles x 2 ntiles (+bias,relu)
  tt_gemm<<<dim3(4, nb), 256, smem>>>(pH12, pM1, 262144LL, out, 65536LL, 1024,
                                      bias);
}